// round 12
// baseline (speedup 1.0000x reference)
#include <cuda_runtime.h>
#include <math_constants.h>
#include <cstdint>

// Problem: votes (16,6,6,3,3,32,32,4,4); EM routing, 2 iterations.
// Cluster of 2 CTAs per position; CTA q owns i in [16q, 16q+16).
// 1024 threads, occ 1, ~218KB smem: j<4 sub-slabs staged in SMEM during pass A;
// fused pass reads j<4 from SMEM (29cyc) and j>=4 from L2 (42MB resident).
#define NPOS   576
#define KHW    9
#define OO     32
#define KDIM   288
#define PERPOS (KDIM*512)
#define EPSC   1e-7f
#define INVT1  0.0005f        // 0.01*(1-0.95^1)
#define INVT2  0.00142625f    // 0.01*(1-0.95^3)

#define NT     1024
#define JS     4              // j-slabs staged in SMEM per i (of 9)

// smem layout (floats)
#define OFF_V     0                    // 16*JS*512 = 32768 (staged V)
#define OFF_G     32768                // 32*272 = 8704 (per-warp crv partials; pass-A alias 8192)
#define OFF_G2    41472                // 8704
#define OFF_R1    50176                // 288
#define OFF_A8    50464                // 288
#define OFF_Q2T   50752                // 528  [aa*33+o]
#define OFF_MQ1T  51280                // 528
#define OFF_BASE  51808                // 32
#define OFF_S1    51840                // 8
#define OFF_AV    51848                // 544  [o*17+aa]
#define OFF_AV2   52392                // 544
#define OFF_AVF   52936                // 544
#define OFF_AV2F  53480                // 544
#define OFF_GR    54024                // 512  [w*16+m]
#define OFF_SE    54536                // 32   [w]
#define OFF_FA    54568                // 544
#define OFF_FB    55112                // 544
#define OFF_FC    55656                // 32
#define SMEM_FLOATS 55688
#define SMEM_BYTES  (SMEM_FLOATS*4)    // 222752 B

extern __shared__ float smem[];

__device__ __forceinline__ uint64_t pk2(float lo, float hi) {
    uint64_t r; asm("mov.b64 %0, {%1, %2};" : "=l"(r) : "f"(lo), "f"(hi)); return r;
}
__device__ __forceinline__ void upk2(uint64_t p, float& lo, float& hi) {
    asm("mov.b64 {%0, %1}, %2;" : "=f"(lo), "=f"(hi) : "l"(p));
}
__device__ __forceinline__ uint64_t mul2(uint64_t a, uint64_t b) {
    uint64_t r; asm("mul.rn.f32x2 %0, %1, %2;" : "=l"(r) : "l"(a), "l"(b)); return r;
}
__device__ __forceinline__ uint64_t add2(uint64_t a, uint64_t b) {
    uint64_t r; asm("add.rn.f32x2 %0, %1, %2;" : "=l"(r) : "l"(a), "l"(b)); return r;
}
__device__ __forceinline__ uint64_t fma2(uint64_t a, uint64_t b, uint64_t c) {
    uint64_t r; asm("fma.rn.f32x2 %0, %1, %2, %3;" : "=l"(r) : "l"(a), "l"(b), "l"(c)); return r;
}
__device__ __forceinline__ void bar_group(int id) {   // 4-warp named barrier
    asm volatile("bar.sync %0, 128;" :: "r"(id) : "memory");
}
__device__ __forceinline__ uint32_t smem_u32(const void* p) {
    uint32_t r;
    asm("{ .reg .u64 t; cvta.to.shared.u64 t, %1; cvt.u32.u64 %0, t; }"
        : "=r"(r) : "l"(p));
    return r;
}
__device__ __forceinline__ uint32_t mapa_rank(uint32_t addr, uint32_t rank) {
    uint32_t r;
    asm("mapa.shared::cluster.u32 %0, %1, %2;" : "=r"(r) : "r"(addr), "r"(rank));
    return r;
}
__device__ __forceinline__ float ld_dsm(uint32_t addr) {
    float v;
    asm volatile("ld.shared::cluster.f32 %0, [%1];" : "=f"(v) : "r"(addr));
    return v;
}
__device__ __forceinline__ void cluster_sync() {
    asm volatile("barrier.cluster.arrive.aligned;" ::: "memory");
    asm volatile("barrier.cluster.wait.aligned;"   ::: "memory");
}
__device__ __forceinline__ uint32_t ctarank() {
    uint32_t r;
    asm("mov.u32 %0, %%cluster_ctarank;" : "=r"(r));
    return r;
}

__global__ __launch_bounds__(NT, 1) __cluster_dims__(2, 1, 1)
void em_routing_kernel(const float* __restrict__ votes,
                       const float* __restrict__ activ,
                       const float* __restrict__ beta_a,
                       const float* __restrict__ beta_u,
                       float* __restrict__ out)
{
    float* s_V    = smem + OFF_V;
    float* s_G    = smem + OFF_G;
    float* s_G2   = smem + OFF_G2;
    float* s_R1   = smem + OFF_R1;
    float* s_a8   = smem + OFF_A8;
    float* s_q2T  = smem + OFF_Q2T;
    float* s_mq1T = smem + OFF_MQ1T;
    float* s_base = smem + OFF_BASE;
    float* s_S1   = smem + OFF_S1;
    float* s_av   = smem + OFF_AV;
    float* s_av2  = smem + OFF_AV2;
    float* s_avF  = smem + OFF_AVF;
    float* s_av2F = smem + OFF_AV2F;
    float* s_gr   = smem + OFF_GR;
    float* s_se   = smem + OFF_SE;
    float* s_fA   = smem + OFF_FA;
    float* s_fB   = smem + OFF_FB;
    float* s_fC   = smem + OFF_FC;
    float* s_pA   = s_G;               // pass-A slice partials alias (8192 <= 8704)

    const int t    = threadIdx.x;      // 0..1023
    const int q    = (int)ctarank();   // 0 or 1
    const int peer = q ^ 1;
    const int q16  = 16 * q;
    const int pos  = blockIdx.x >> 1;
    const float* __restrict__ V  = votes + (int64_t)pos * PERPOS;
    const float* __restrict__ Ai = activ + pos * KDIM;

    // ---- prologue ----
    if (t < KDIM) {
        float a = Ai[t];
        s_a8[t] = 0.8f * a;
        s_R1[t] = (0.8f * a + 0.2f) * (1.0f / 32.0f);
    }
    __syncthreads();
    if (t < 32) {
        float s = 0.f;
        #pragma unroll
        for (int k = t; k < KDIM; k += 32) s += s_R1[k];
        #pragma unroll
        for (int off = 16; off; off >>= 1) s += __shfl_xor_sync(0xffffffffu, s, off);
        if (t == 0) s_S1[0] = s;
    }

    // ---- Pass A over own 16 i's: slice sl covers i_l in {2sl, 2sl+1}, all j.
    //      Write-through j<JS sub-slabs into SMEM while reducing. ----
    {
        const int sl = t >> 7;           // 0..7
        const int c0 = (t & 127) * 4;
        uint64_t av0 = 0, av1 = 0, av20 = 0, av21 = 0;
        #pragma unroll
        for (int a = 0; a < 2; ++a) {
            const int i_l = sl * 2 + a;
            const ulonglong2* gv =
                (const ulonglong2*)(V + (size_t)(q16 + i_l) * 512 + c0);
            const float* r1 = s_R1 + q16 + i_l;
            #pragma unroll
            for (int j = 0; j < KHW; ++j) {
                ulonglong2 v = gv[(size_t)j * 32 * 128];
                if (j < JS)
                    *(ulonglong2*)(s_V + (i_l * JS + j) * 512 + c0) = v;
                float r = r1[j * 32];
                uint64_t r2  = pk2(r, r);
                uint64_t rv0 = mul2(r2, v.x);
                uint64_t rv1 = mul2(r2, v.y);
                av0  = add2(av0, rv0);
                av1  = add2(av1, rv1);
                av20 = fma2(rv0, v.x, av20);
                av21 = fma2(rv1, v.y, av21);
            }
        }
        ulonglong2 st;
        st.x = av0;  st.y = av1;
        *(ulonglong2*)(s_pA + sl * 1024 + c0) = st;
        st.x = av20; st.y = av21;
        *(ulonglong2*)(s_pA + sl * 1024 + 512 + c0) = st;
    }
    __syncthreads();

    // ---- local combine -> per-(o,aa) own-half partials ----
    if (t < 512) {
        float av = 0.f, av2 = 0.f;
        #pragma unroll
        for (int ss = 0; ss < 8; ++ss) {
            av  += s_pA[ss * 1024 + t];
            av2 += s_pA[ss * 1024 + 512 + t];
        }
        const int idx = (t >> 4) * 17 + (t & 15);
        s_av [idx] = av;
        s_av2[idx] = av2;
    }
    cluster_sync();   // #1: partials visible to peer

    // ---- stats: combine halves (redundant in both CTAs), build tables ----
    if (t < 512) {
        const int o   = t >> 4;
        const int aa  = t & 15;
        const int idx = o * 17 + aa;
        const float av  = s_av [idx] + ld_dsm(mapa_rank(smem_u32(s_av)  + idx * 4, peer));
        const float av2 = s_av2[idx] + ld_dsm(mapa_rank(smem_u32(s_av2) + idx * 4, peer));
        s_avF [idx] = av;
        s_av2F[idx] = av2;
        const float S1    = s_S1[0];
        const float invS1 = 1.0f / (S1 + EPSC);
        const float mu1   = av * invS1;
        const float sig1  = fmaf(mu1 * mu1, S1, fmaf(-2.0f * mu1, av, av2)) * invS1;
        const float i2s1  = 0.5f / sig1;           // 1/(2 sigma^2), no eps (ref)
        const float q1    = mu1 * i2s1;
        s_q2T [aa * 33 + o] = i2s1;
        s_mq1T[aa * 33 + o] = -2.0f * q1;

        float Co   = mu1 * q1;
        float cc0  = __logf(fmaf(2.0f * CUDART_PI_F, sig1, EPSC));
        float cost = (beta_u[o] - 0.5f * __logf(sig1 + EPSC)) * S1;
        #pragma unroll
        for (int off = 8; off; off >>= 1) {
            Co   += __shfl_xor_sync(0xffffffffu, Co,   off);
            cc0  += __shfl_xor_sync(0xffffffffu, cc0,  off);
            cost += __shfl_xor_sync(0xffffffffu, cost, off);
        }
        if (aa == 0) {
            float arg = INVT1 * (beta_a[o] - cost);
            float aj  = 1.0f / (1.0f + __expf(-arg));
            s_base[o] = __logf(aj + EPSC) - cc0 - Co;
        }
    }
    __syncthreads();   // tables ready; orders s_pA reads before s_G reuse

    // ---- Fused E-step + M-step-2: 32 warps, warp w = (h = w>>4, i_l = w&15).
    //      Single round. j<JS from SMEM, j>=JS from L2. Pair {w, w^16} shares i. ----
    {
        const int w   = t >> 5;
        const int l   = t & 31;
        const int h   = w >> 4;
        const int il  = w & 15;
        const int m   = l & 15;
        const int ah  = l >> 4;
        const int o   = h * 16 + m;
        const int i   = q16 + il;
        const int bid = (il & 7) + 1;     // 4 warps per barrier id (2 se-pairs)

        uint64_t q2p[4], mqp[4];
        #pragma unroll
        for (int p = 0; p < 4; ++p) {
            const int aa0 = ah * 8 + 2 * p;
            q2p[p] = pk2(s_q2T [aa0 * 33 + o], s_q2T [(aa0 + 1) * 33 + o]);
            mqp[p] = pk2(s_mq1T[aa0 * 33 + o], s_mq1T[(aa0 + 1) * 33 + o]);
        }
        const float base = s_base[o];

        uint64_t g0 = 0, g1 = 0, g2 = 0, g3 = 0;
        uint64_t e0 = 0, e1 = 0, e2 = 0, e3 = 0;
        float gr = 0.f, se = 0.f;
        const int coff = o * 16 + ah * 8;

        // helper macro: process one (j) slab given va/vb
        #define EM_BODY(va, vb, jj)                                           \
        {                                                                     \
            uint64_t t2 = 0;                                                  \
            t2 = fma2(va.x, fma2(va.x, q2p[0], mqp[0]), t2);                  \
            t2 = fma2(va.y, fma2(va.y, q2p[1], mqp[1]), t2);                  \
            t2 = fma2(vb.x, fma2(vb.x, q2p[2], mqp[2]), t2);                  \
            t2 = fma2(vb.y, fma2(vb.y, q2p[3], mqp[3]), t2);                  \
            float tlo, thi;                                                   \
            upk2(t2, tlo, thi);                                               \
            float term = tlo + thi;                                           \
            term += __shfl_xor_sync(0xffffffffu, term, 16);                   \
            float e = __expf(base - term);                                    \
            se += e;                                                          \
            float ep = s_a8[(jj) * 32 + i] * e;                               \
            gr += ep;                                                         \
            uint64_t ep2 = pk2(ep, ep);                                       \
            uint64_t rv;                                                      \
            rv = mul2(ep2, va.x); g0 = add2(g0, rv); e0 = fma2(rv, va.x, e0); \
            rv = mul2(ep2, va.y); g1 = add2(g1, rv); e1 = fma2(rv, va.y, e1); \
            rv = mul2(ep2, vb.x); g2 = add2(g2, rv); e2 = fma2(rv, vb.x, e2); \
            rv = mul2(ep2, vb.y); g3 = add2(g3, rv); e3 = fma2(rv, vb.y, e3); \
        }

        #pragma unroll
        for (int j = 0; j < JS; ++j) {        // SMEM-staged slabs
            const ulonglong2* sv =
                (const ulonglong2*)(s_V + (il * JS + j) * 512 + coff);
            ulonglong2 va = sv[0];
            ulonglong2 vb = sv[1];
            EM_BODY(va, vb, j)
        }
        #pragma unroll
        for (int j = JS; j < KHW; ++j) {      // L2-resident slabs
            const ulonglong2* pv =
                (const ulonglong2*)(V + (size_t)(j * 32 + i) * 512 + coff);
            ulonglong2 va = pv[0];
            ulonglong2 vb = pv[1];
            EM_BODY(va, vb, j)
        }
        #undef EM_BODY

        // se over warp (each e counted twice by the two ah lanes)
        #pragma unroll
        for (int off = 16; off; off >>= 1)
            se += __shfl_xor_sync(0xffffffffu, se, off);
        if (l == 0) s_se[w] = se;
        bar_group(bid);                       // 4-warp barrier
        const float invs = 1.0f / (0.5f * (s_se[w] + s_se[w ^ 16]));

        float* Gp  = s_G  + w * 272 + m * 17 + ah * 8;
        float* G2p = s_G2 + w * 272 + m * 17 + ah * 8;
        float lo, hi;
        upk2(g0, lo, hi); Gp [0] = invs*lo; Gp [1] = invs*hi;
        upk2(g1, lo, hi); Gp [2] = invs*lo; Gp [3] = invs*hi;
        upk2(g2, lo, hi); Gp [4] = invs*lo; Gp [5] = invs*hi;
        upk2(g3, lo, hi); Gp [6] = invs*lo; Gp [7] = invs*hi;
        upk2(e0, lo, hi); G2p[0] = invs*lo; G2p[1] = invs*hi;
        upk2(e1, lo, hi); G2p[2] = invs*lo; G2p[3] = invs*hi;
        upk2(e2, lo, hi); G2p[4] = invs*lo; G2p[5] = invs*hi;
        upk2(e3, lo, hi); G2p[6] = invs*lo; G2p[7] = invs*hi;
        if (ah == 0) s_gr[w * 16 + m] = invs * gr;
    }
    __syncthreads();

    // ---- local e-part combine per (o,aa) over this CTA's 16 i-warps ----
    if (t < 512) {
        const int o   = t >> 4;
        const int aa  = t & 15;
        const int h   = o >> 4;
        const int m   = o & 15;
        const int idx = o * 17 + aa;
        float crv = 0.f, crv2 = 0.f, cr = 0.f;
        #pragma unroll
        for (int il = 0; il < 16; ++il) {
            const int w = h * 16 + il;
            crv  += s_G [w * 272 + m * 17 + aa];
            crv2 += s_G2[w * 272 + m * 17 + aa];
            cr   += s_gr[w * 16 + m];
        }
        s_fA[idx] = crv;
        s_fB[idx] = crv2;
        if (aa == 0) s_fC[o] = cr;
    }
    cluster_sync();   // #2: e-partials visible to peer

    // ---- output: CTA q writes o in [16q, 16q+16) ----
    if (t < 256) {
        const int o   = q16 + (t >> 4);
        const int aa  = t & 15;
        const int idx = o * 17 + aa;
        float crv  = s_fA[idx] + ld_dsm(mapa_rank(smem_u32(s_fA) + idx * 4, peer))
                   + 0.2f * s_avF[idx];
        float crv2 = s_fB[idx] + ld_dsm(mapa_rank(smem_u32(s_fB) + idx * 4, peer))
                   + 0.2f * s_av2F[idx];
        float cr   = s_fC[o] + ld_dsm(mapa_rank(smem_u32(s_fC) + o * 4, peer))
                   + 0.2f * s_S1[0];

        const float invR = 1.0f / (cr + EPSC);
        const float mu2  = crv * invR;
        out[pos * 512 + o * 16 + aa] = mu2;                        // poses

        const float sig2 = fmaf(mu2 * mu2, cr, fmaf(-2.0f * mu2, crv, crv2)) * invR;
        float cost2 = (beta_u[o] - 0.5f * __logf(sig2 + EPSC)) * cr;
        #pragma unroll
        for (int off = 8; off; off >>= 1)
            cost2 += __shfl_xor_sync(0xffffffffu, cost2, off);
        if (aa == 0) {
            float arg = INVT2 * (beta_a[o] - cost2);
            out[NPOS * 512 + pos * OO + o] = 1.0f / (1.0f + __expf(-arg)); // acts
        }
    }

    cluster_sync();   // #3: peer may still read our smem
}

extern "C" void kernel_launch(void* const* d_in, const int* in_sizes, int n_in,
                              void* d_out, int out_size) {
    const float* votes  = (const float*)d_in[0];
    const float* activ  = (const float*)d_in[1];
    const float* beta_a = (const float*)d_in[2];
    const float* beta_u = (const float*)d_in[3];

    cudaFuncSetAttribute(em_routing_kernel,
                         cudaFuncAttributeMaxDynamicSharedMemorySize,
                         SMEM_BYTES);

    em_routing_kernel<<<NPOS * 2, NT, SMEM_BYTES>>>(
        votes, activ, beta_a, beta_u, (float*)d_out);
}

// round 13
// speedup vs baseline: 1.1658x; 1.1658x over previous
#include <cuda_runtime.h>
#include <math_constants.h>
#include <cstdint>

// EM routing, votes (16,6,6,3,3,32,32,4,4), 2 iterations.
// Warp-specialized persistent kernel: 144 CTAs x 1024 thr, 4 positions each.
// Producer warps (t<512) stream pass A of position n(+1) from HBM into stats.
// Consumer warps (t>=512) run fused E+M pass of position n from L2.
#define NPOS   576
#define KHW    9
#define OO     32
#define KDIM   288
#define PERPOS (KDIM*512)
#define EPSC   1e-7f
#define INVT1  0.0005f        // 0.01*(1-0.95^1)
#define INVT2  0.00142625f    // 0.01*(1-0.95^3)

#define NT     1024
#define NCTA   144
#define POSPER 4

// stats buffer layout (floats)
#define ST_Q2   0      // 528  [aa*33+o]
#define ST_MQ1  528    // 528
#define ST_BASE 1056   // 32
#define ST_A8   1088   // 288
#define ST_AVF  1376   // 544  [o*17+aa]
#define ST_AV2F 1920   // 544
#define ST_S1   2464   // 8
#define ST_SIZE 2472

// smem layout (floats)
#define OFF_PA  0                       // 4096 producer slice partials
#define OFF_R1  4096                    // 288
#define OFF_ST  4384                    // 2*2472 = 4944
#define OFF_G   (OFF_ST + 2*ST_SIZE)    // 4352  consumer crv partials
#define OFF_G2  (OFF_G + 4352)          // 4352
#define OFF_GR  (OFF_G2 + 4352)         // 256
#define OFF_SE  (OFF_GR + 256)          // 64
#define SMEM_FLOATS (OFF_SE + 64)
#define SMEM_BYTES  (SMEM_FLOATS*4)     // ~74KB

extern __shared__ float smem[];

__device__ __forceinline__ uint64_t pk2(float lo, float hi) {
    uint64_t r; asm("mov.b64 %0, {%1, %2};" : "=l"(r) : "f"(lo), "f"(hi)); return r;
}
__device__ __forceinline__ void upk2(uint64_t p, float& lo, float& hi) {
    asm("mov.b64 {%0, %1}, %2;" : "=f"(lo), "=f"(hi) : "l"(p));
}
__device__ __forceinline__ uint64_t mul2(uint64_t a, uint64_t b) {
    uint64_t r; asm("mul.rn.f32x2 %0, %1, %2;" : "=l"(r) : "l"(a), "l"(b)); return r;
}
__device__ __forceinline__ uint64_t add2(uint64_t a, uint64_t b) {
    uint64_t r; asm("add.rn.f32x2 %0, %1, %2;" : "=l"(r) : "l"(a), "l"(b)); return r;
}
__device__ __forceinline__ uint64_t fma2(uint64_t a, uint64_t b, uint64_t c) {
    uint64_t r; asm("fma.rn.f32x2 %0, %1, %2, %3;" : "=l"(r) : "l"(a), "l"(b), "l"(c)); return r;
}
__device__ __forceinline__ void bar_sync(int id, int cnt) {
    asm volatile("bar.sync %0, %1;" :: "r"(id), "r"(cnt) : "memory");
}
__device__ __forceinline__ void bar_arrive(int id, int cnt) {
    asm volatile("bar.arrive %0, %1;" :: "r"(id), "r"(cnt) : "memory");
}

// barrier ids: FULL[b]=1+b, FREE[b]=3+b, producer=5, consumer=6, pair=8+ib
#define BAR_FULL(b) (1 + (b))
#define BAR_FREE(b) (3 + (b))
#define BAR_PROD    5
#define BAR_CONS    6

__global__ __launch_bounds__(NT, 1)
void em_routing_kernel(const float* __restrict__ votes,
                       const float* __restrict__ activ,
                       const float* __restrict__ beta_a,
                       const float* __restrict__ beta_u,
                       float* __restrict__ out)
{
    float* s_pA = smem + OFF_PA;
    float* s_R1 = smem + OFF_R1;
    float* s_G  = smem + OFF_G;
    float* s_G2 = smem + OFF_G2;
    float* s_gr = smem + OFF_GR;
    float* s_se = smem + OFF_SE;

    const int t    = threadIdx.x;                 // 0..1023
    const int base = blockIdx.x * POSPER;

    if (t < 512) {
        // ================= PRODUCER: pass A + stats closure =================
        for (int n = 0; n < POSPER; ++n) {
            const int   pos = base + n;
            const int   b   = n & 1;
            float* st = smem + OFF_ST + b * ST_SIZE;
            const float* __restrict__ V  = votes + (int64_t)pos * PERPOS;
            const float* __restrict__ Ai = activ + pos * KDIM;

            if (n >= 2) bar_sync(BAR_FREE(b), 1024);   // consumers freed buffer

            // prologue: R1 (private) + a8 (into stats buffer)
            if (t < KDIM) {
                float a = Ai[t];
                st[ST_A8 + t] = 0.8f * a;
                s_R1[t] = (0.8f * a + 0.2f) * (1.0f / 32.0f);
            }
            bar_sync(BAR_PROD, 512);
            if (t < 32) {
                float s = 0.f;
                #pragma unroll
                for (int k = t; k < KDIM; k += 32) s += s_R1[k];
                #pragma unroll
                for (int off = 16; off; off >>= 1)
                    s += __shfl_xor_sync(0xffffffffu, s, off);
                if (t == 0) st[ST_S1] = s;
            }

            // pass A: slice sl = t>>7 covers k in [72sl, 72sl+72)
            {
                const int sl = t >> 7;
                const int c0 = (t & 127) * 4;
                const ulonglong2* gv =
                    (const ulonglong2*)(V + (size_t)(sl * 72) * 512 + c0);
                const float* r1 = s_R1 + sl * 72;
                uint64_t av0 = 0, av1 = 0, av20 = 0, av21 = 0;
                #pragma unroll 8
                for (int k = 0; k < 72; ++k) {
                    ulonglong2 v = gv[(size_t)k * 128];
                    float r = r1[k];
                    uint64_t r2  = pk2(r, r);
                    uint64_t rv0 = mul2(r2, v.x);
                    uint64_t rv1 = mul2(r2, v.y);
                    av0  = add2(av0, rv0);
                    av1  = add2(av1, rv1);
                    av20 = fma2(rv0, v.x, av20);
                    av21 = fma2(rv1, v.y, av21);
                }
                ulonglong2 w;
                w.x = av0;  w.y = av1;
                *(ulonglong2*)(s_pA + sl * 1024 + c0) = w;
                w.x = av20; w.y = av21;
                *(ulonglong2*)(s_pA + sl * 1024 + 512 + c0) = w;
            }
            bar_sync(BAR_PROD, 512);

            // stats closure: thread t = (o,aa)
            {
                float av = 0.f, av2 = 0.f;
                #pragma unroll
                for (int ss = 0; ss < 4; ++ss) {
                    av  += s_pA[ss * 1024 + t];
                    av2 += s_pA[ss * 1024 + 512 + t];
                }
                const int   o     = t >> 4;
                const int   aa    = t & 15;
                const float S1    = st[ST_S1];
                const float invS1 = 1.0f / (S1 + EPSC);
                const float mu1   = av * invS1;
                const float sig1  =
                    fmaf(mu1 * mu1, S1, fmaf(-2.0f * mu1, av, av2)) * invS1;
                const float i2s1  = 0.5f / sig1;      // no eps (matches ref)
                const float q1    = mu1 * i2s1;
                st[ST_Q2  + aa * 33 + o] = i2s1;
                st[ST_MQ1 + aa * 33 + o] = -2.0f * q1;
                st[ST_AVF  + o * 17 + aa] = av;
                st[ST_AV2F + o * 17 + aa] = av2;

                float Co   = mu1 * q1;
                float cc0  = __logf(fmaf(2.0f * CUDART_PI_F, sig1, EPSC));
                float cost = (beta_u[o] - 0.5f * __logf(sig1 + EPSC)) * S1;
                #pragma unroll
                for (int off = 8; off; off >>= 1) {
                    Co   += __shfl_xor_sync(0xffffffffu, Co,   off);
                    cc0  += __shfl_xor_sync(0xffffffffu, cc0,  off);
                    cost += __shfl_xor_sync(0xffffffffu, cost, off);
                }
                if (aa == 0) {
                    float arg = INVT1 * (beta_a[o] - cost);
                    float aj  = 1.0f / (1.0f + __expf(-arg));
                    st[ST_BASE + o] = __logf(aj + EPSC) - cc0 - Co;
                }
            }
            __threadfence_block();
            bar_arrive(BAR_FULL(b), 1024);     // stats[b] ready
        }
    } else {
        // ================= CONSUMER: fused E-step + M-step-2 =================
        const int wc = (t >> 5) - 16;        // 0..15
        const int l  = t & 31;
        const int h  = wc >> 3;              // o-half
        const int ib = wc & 7;
        const int m  = l & 15;
        const int ah = l >> 4;
        const int o  = h * 16 + m;
        float* Gp  = s_G  + wc * 272 + m * 17 + ah * 8;
        float* G2p = s_G2 + wc * 272 + m * 17 + ah * 8;

        for (int n = 0; n < POSPER; ++n) {
            const int pos = base + n;
            const int b   = n & 1;
            const float* st = smem + OFF_ST + b * ST_SIZE;
            const float* __restrict__ V = votes + (int64_t)pos * PERPOS;

            bar_sync(BAR_FULL(b), 1024);       // wait stats[b]

            uint64_t q2p[4], mqp[4];
            #pragma unroll
            for (int p = 0; p < 4; ++p) {
                const int aa0 = ah * 8 + 2 * p;
                q2p[p] = pk2(st[ST_Q2  + aa0 * 33 + o], st[ST_Q2  + (aa0+1) * 33 + o]);
                mqp[p] = pk2(st[ST_MQ1 + aa0 * 33 + o], st[ST_MQ1 + (aa0+1) * 33 + o]);
            }
            const float bse = st[ST_BASE + o];
            const float* sA8 = st + ST_A8;
            const int coff = o * 16 + ah * 8;

            #pragma unroll
            for (int r = 0; r < 4; ++r) {
                const int i = ib + 8 * r;
                uint64_t g0 = 0, g1 = 0, g2 = 0, g3 = 0;
                uint64_t e0 = 0, e1 = 0, e2 = 0, e3 = 0;
                float gr = 0.f, se = 0.f;

                #pragma unroll
                for (int j = 0; j < KHW; ++j) {
                    const ulonglong2* pv = (const ulonglong2*)
                        (V + (size_t)(j * 32 + i) * 512 + coff);
                    ulonglong2 va = pv[0];
                    ulonglong2 vb = pv[1];
                    uint64_t t2 = 0;
                    t2 = fma2(va.x, fma2(va.x, q2p[0], mqp[0]), t2);
                    t2 = fma2(va.y, fma2(va.y, q2p[1], mqp[1]), t2);
                    t2 = fma2(vb.x, fma2(vb.x, q2p[2], mqp[2]), t2);
                    t2 = fma2(vb.y, fma2(vb.y, q2p[3], mqp[3]), t2);
                    float tlo, thi;
                    upk2(t2, tlo, thi);
                    float term = tlo + thi;
                    term += __shfl_xor_sync(0xffffffffu, term, 16); // join aa-halves
                    float e = __expf(bse - term);   // un-normalized, fp32-safe
                    se += e;
                    float ep = sA8[j * 32 + i] * e;
                    gr += ep;
                    uint64_t ep2 = pk2(ep, ep);
                    uint64_t rv;
                    rv = mul2(ep2, va.x); g0 = add2(g0, rv); e0 = fma2(rv, va.x, e0);
                    rv = mul2(ep2, va.y); g1 = add2(g1, rv); e1 = fma2(rv, va.y, e1);
                    rv = mul2(ep2, vb.x); g2 = add2(g2, rv); e2 = fma2(rv, vb.x, e2);
                    rv = mul2(ep2, vb.y); g3 = add2(g3, rv); e3 = fma2(rv, vb.y, e3);
                }

                // se over warp (each e counted twice by the two ah lanes)
                #pragma unroll
                for (int off = 16; off; off >>= 1)
                    se += __shfl_xor_sync(0xffffffffu, se, off);
                if (l == 0) s_se[r * 16 + wc] = se;
                bar_sync(8 + ib, 64);           // pair {wc, wc^8}
                const float invs =
                    1.0f / (0.5f * (s_se[r * 16 + wc] + s_se[r * 16 + (wc ^ 8)]));

                float lo, hi;
                if (r == 0) {
                    upk2(g0, lo, hi); Gp [0] = invs*lo; Gp [1] = invs*hi;
                    upk2(g1, lo, hi); Gp [2] = invs*lo; Gp [3] = invs*hi;
                    upk2(g2, lo, hi); Gp [4] = invs*lo; Gp [5] = invs*hi;
                    upk2(g3, lo, hi); Gp [6] = invs*lo; Gp [7] = invs*hi;
                    upk2(e0, lo, hi); G2p[0] = invs*lo; G2p[1] = invs*hi;
                    upk2(e1, lo, hi); G2p[2] = invs*lo; G2p[3] = invs*hi;
                    upk2(e2, lo, hi); G2p[4] = invs*lo; G2p[5] = invs*hi;
                    upk2(e3, lo, hi); G2p[6] = invs*lo; G2p[7] = invs*hi;
                    if (ah == 0) s_gr[wc * 16 + m] = invs * gr;
                } else {
                    upk2(g0, lo, hi); Gp [0] += invs*lo; Gp [1] += invs*hi;
                    upk2(g1, lo, hi); Gp [2] += invs*lo; Gp [3] += invs*hi;
                    upk2(g2, lo, hi); Gp [4] += invs*lo; Gp [5] += invs*hi;
                    upk2(g3, lo, hi); Gp [6] += invs*lo; Gp [7] += invs*hi;
                    upk2(e0, lo, hi); G2p[0] += invs*lo; G2p[1] += invs*hi;
                    upk2(e1, lo, hi); G2p[2] += invs*lo; G2p[3] += invs*hi;
                    upk2(e2, lo, hi); G2p[4] += invs*lo; G2p[5] += invs*hi;
                    upk2(e3, lo, hi); G2p[6] += invs*lo; G2p[7] += invs*hi;
                    if (ah == 0) s_gr[wc * 16 + m] += invs * gr;
                }
            }
            bar_sync(BAR_CONS, 512);           // G/G2/gr complete

            // final closure + output: consumer thread co = (o2, aa2)
            {
                const int co  = t - 512;
                const int o2  = co >> 4;
                const int aa2 = co & 15;
                const int h2  = o2 >> 4;
                const int m2  = o2 & 15;
                float crv  = 0.2f * st[ST_AVF  + o2 * 17 + aa2];
                float crv2 = 0.2f * st[ST_AV2F + o2 * 17 + aa2];
                float cr   = 0.2f * st[ST_S1];
                #pragma unroll
                for (int jb = 0; jb < 8; ++jb) {
                    const int w = h2 * 8 + jb;
                    crv  += s_G [w * 272 + m2 * 17 + aa2];
                    crv2 += s_G2[w * 272 + m2 * 17 + aa2];
                    cr   += s_gr[w * 16 + m2];
                }
                const float invR = 1.0f / (cr + EPSC);
                const float mu2  = crv * invR;
                out[pos * 512 + o2 * 16 + aa2] = mu2;             // poses

                const float sig2 =
                    fmaf(mu2 * mu2, cr, fmaf(-2.0f * mu2, crv, crv2)) * invR;
                float cost2 = (beta_u[o2] - 0.5f * __logf(sig2 + EPSC)) * cr;
                #pragma unroll
                for (int off = 8; off; off >>= 1)
                    cost2 += __shfl_xor_sync(0xffffffffu, cost2, off);
                if (aa2 == 0) {
                    float arg = INVT2 * (beta_a[o2] - cost2);
                    out[NPOS * 512 + pos * OO + o2] =
                        1.0f / (1.0f + __expf(-arg));             // acts
                }
            }
            bar_sync(BAR_CONS, 512);           // closure reads done before next n
            if (n < 2) bar_arrive(BAR_FREE(b), 1024);   // release stats[b]
        }
    }
}

extern "C" void kernel_launch(void* const* d_in, const int* in_sizes, int n_in,
                              void* d_out, int out_size) {
    const float* votes  = (const float*)d_in[0];
    const float* activ  = (const float*)d_in[1];
    const float* beta_a = (const float*)d_in[2];
    const float* beta_u = (const float*)d_in[3];

    cudaFuncSetAttribute(em_routing_kernel,
                         cudaFuncAttributeMaxDynamicSharedMemorySize,
                         SMEM_BYTES);

    em_routing_kernel<<<NCTA, NT, SMEM_BYTES>>>(
        votes, activ, beta_a, beta_u, (float*)d_out);
}

// round 15
// speedup vs baseline: 1.3942x; 1.1959x over previous
#include <cuda_runtime.h>
#include <math_constants.h>
#include <cstdint>

// EM routing, votes (16,6,6,3,3,32,32,4,4), 2 iterations.
// Warp-specialized persistent kernel: 144 CTAs x 1024 thr, 4 positions each.
// Producer warps (t<512) stream pass A of position n(+1) from HBM (evict_last).
// Consumer warps (t>=512) run fused E+M pass of position n from L2 (evict_first).
// L2 eviction hints require 256-bit loads on sm_103a -> v4.b64 everywhere.
#define NPOS   576
#define KHW    9
#define OO     32
#define KDIM   288
#define PERPOS (KDIM*512)
#define EPSC   1e-7f
#define INVT1  0.0005f        // 0.01*(1-0.95^1)
#define INVT2  0.00142625f    // 0.01*(1-0.95^3)

#define NT     1024
#define NCTA   144
#define POSPER 4

// stats buffer layout (floats)
#define ST_Q2   0      // 528  [aa*33+o]
#define ST_MQ1  528    // 528
#define ST_BASE 1056   // 32
#define ST_A8   1088   // 288
#define ST_AVF  1376   // 544  [o*17+aa]
#define ST_AV2F 1920   // 544
#define ST_S1   2464   // 8
#define ST_SIZE 2472

// smem layout (floats)
#define OFF_PA  0                       // 8192 producer slice partials (8 slices)
#define OFF_R1  8192                    // 288
#define OFF_ST  8480                    // 2*2472 = 4944
#define OFF_G   (OFF_ST + 2*ST_SIZE)    // 4352  consumer crv partials
#define OFF_G2  (OFF_G + 4352)          // 4352
#define OFF_GR  (OFF_G2 + 4352)         // 256
#define OFF_SE  (OFF_GR + 256)          // 64
#define SMEM_FLOATS (OFF_SE + 64)
#define SMEM_BYTES  (SMEM_FLOATS*4)     // ~90KB

extern __shared__ float smem[];

struct U64x4 { uint64_t a, b, c, d; };

__device__ __forceinline__ uint64_t pk2(float lo, float hi) {
    uint64_t r; asm("mov.b64 %0, {%1, %2};" : "=l"(r) : "f"(lo), "f"(hi)); return r;
}
__device__ __forceinline__ void upk2(uint64_t p, float& lo, float& hi) {
    asm("mov.b64 {%0, %1}, %2;" : "=f"(lo), "=f"(hi) : "l"(p));
}
__device__ __forceinline__ uint64_t mul2(uint64_t a, uint64_t b) {
    uint64_t r; asm("mul.rn.f32x2 %0, %1, %2;" : "=l"(r) : "l"(a), "l"(b)); return r;
}
__device__ __forceinline__ uint64_t add2(uint64_t a, uint64_t b) {
    uint64_t r; asm("add.rn.f32x2 %0, %1, %2;" : "=l"(r) : "l"(a), "l"(b)); return r;
}
__device__ __forceinline__ uint64_t fma2(uint64_t a, uint64_t b, uint64_t c) {
    uint64_t r; asm("fma.rn.f32x2 %0, %1, %2, %3;" : "=l"(r) : "l"(a), "l"(b), "l"(c)); return r;
}
// 256-bit streaming loads with L2 eviction-priority steering
__device__ __forceinline__ U64x4 ldg_last32(const void* p) {   // producer
    U64x4 v;
    asm volatile("ld.global.L2::evict_last.v4.b64 {%0, %1, %2, %3}, [%4];"
                 : "=l"(v.a), "=l"(v.b), "=l"(v.c), "=l"(v.d) : "l"(p));
    return v;
}
__device__ __forceinline__ U64x4 ldg_first32(const void* p) {  // consumer
    U64x4 v;
    asm volatile("ld.global.L2::evict_first.v4.b64 {%0, %1, %2, %3}, [%4];"
                 : "=l"(v.a), "=l"(v.b), "=l"(v.c), "=l"(v.d) : "l"(p));
    return v;
}
__device__ __forceinline__ void bar_sync(int id, int cnt) {
    asm volatile("bar.sync %0, %1;" :: "r"(id), "r"(cnt) : "memory");
}
__device__ __forceinline__ void bar_arrive(int id, int cnt) {
    asm volatile("bar.arrive %0, %1;" :: "r"(id), "r"(cnt) : "memory");
}

// barrier ids: FULL[b]=1+b, FREE[b]=3+b, producer=5, consumer=6, pair=8+ib
#define BAR_FULL(b) (1 + (b))
#define BAR_FREE(b) (3 + (b))
#define BAR_PROD    5
#define BAR_CONS    6

__global__ __launch_bounds__(NT, 1)
void em_routing_kernel(const float* __restrict__ votes,
                       const float* __restrict__ activ,
                       const float* __restrict__ beta_a,
                       const float* __restrict__ beta_u,
                       float* __restrict__ out)
{
    float* s_pA = smem + OFF_PA;
    float* s_R1 = smem + OFF_R1;
    float* s_G  = smem + OFF_G;
    float* s_G2 = smem + OFF_G2;
    float* s_gr = smem + OFF_GR;
    float* s_se = smem + OFF_SE;

    const int t    = threadIdx.x;                 // 0..1023
    const int base = blockIdx.x * POSPER;

    if (t < 512) {
        // ================= PRODUCER: pass A + stats closure =================
        for (int n = 0; n < POSPER; ++n) {
            const int   pos = base + n;
            const int   b   = n & 1;
            float* st = smem + OFF_ST + b * ST_SIZE;
            const float* __restrict__ V  = votes + (int64_t)pos * PERPOS;
            const float* __restrict__ Ai = activ + pos * KDIM;

            if (n >= 2) bar_sync(BAR_FREE(b), 1024);   // consumers freed buffer

            // prologue: R1 (private) + a8 (into stats buffer)
            if (t < KDIM) {
                float a = Ai[t];
                st[ST_A8 + t] = 0.8f * a;
                s_R1[t] = (0.8f * a + 0.2f) * (1.0f / 32.0f);
            }
            bar_sync(BAR_PROD, 512);
            if (t < 32) {
                float s = 0.f;
                #pragma unroll
                for (int k = t; k < KDIM; k += 32) s += s_R1[k];
                #pragma unroll
                for (int off = 16; off; off >>= 1)
                    s += __shfl_xor_sync(0xffffffffu, s, off);
                if (t == 0) st[ST_S1] = s;
            }

            // pass A: slice sl = t>>6 (8 slices x 36 k); 32B loads, evict_last
            {
                const int sl = t >> 6;               // 0..7
                const int c0 = (t & 63) * 8;         // 8 owned columns
                const float* gv = V + (size_t)(sl * 36) * 512 + c0;
                const float* r1 = s_R1 + sl * 36;
                uint64_t av0 = 0, av1 = 0, av2a = 0, av3 = 0;
                uint64_t q0 = 0, q1 = 0, q2 = 0, q3 = 0;
                #pragma unroll 6
                for (int k = 0; k < 36; ++k) {
                    U64x4 v = ldg_last32(gv + (size_t)k * 512);
                    float r = r1[k];
                    uint64_t r2 = pk2(r, r);
                    uint64_t rv;
                    rv = mul2(r2, v.a); av0  = add2(av0, rv); q0 = fma2(rv, v.a, q0);
                    rv = mul2(r2, v.b); av1  = add2(av1, rv); q1 = fma2(rv, v.b, q1);
                    rv = mul2(r2, v.c); av2a = add2(av2a, rv); q2 = fma2(rv, v.c, q2);
                    rv = mul2(r2, v.d); av3  = add2(av3, rv); q3 = fma2(rv, v.d, q3);
                }
                ulonglong2 w;
                w.x = av0; w.y = av1;
                *(ulonglong2*)(s_pA + sl * 1024 + c0) = w;
                w.x = av2a; w.y = av3;
                *(ulonglong2*)(s_pA + sl * 1024 + c0 + 4) = w;
                w.x = q0; w.y = q1;
                *(ulonglong2*)(s_pA + sl * 1024 + 512 + c0) = w;
                w.x = q2; w.y = q3;
                *(ulonglong2*)(s_pA + sl * 1024 + 512 + c0 + 4) = w;
            }
            bar_sync(BAR_PROD, 512);

            // stats closure: thread t = (o,aa)
            {
                float av = 0.f, av2 = 0.f;
                #pragma unroll
                for (int ss = 0; ss < 8; ++ss) {
                    av  += s_pA[ss * 1024 + t];
                    av2 += s_pA[ss * 1024 + 512 + t];
                }
                const int   o     = t >> 4;
                const int   aa    = t & 15;
                const float S1    = st[ST_S1];
                const float invS1 = 1.0f / (S1 + EPSC);
                const float mu1   = av * invS1;
                const float sig1  =
                    fmaf(mu1 * mu1, S1, fmaf(-2.0f * mu1, av, av2)) * invS1;
                const float i2s1  = 0.5f / sig1;      // no eps (matches ref)
                const float q1    = mu1 * i2s1;
                st[ST_Q2  + aa * 33 + o] = i2s1;
                st[ST_MQ1 + aa * 33 + o] = -2.0f * q1;
                st[ST_AVF  + o * 17 + aa] = av;
                st[ST_AV2F + o * 17 + aa] = av2;

                float Co   = mu1 * q1;
                float cc0  = __logf(fmaf(2.0f * CUDART_PI_F, sig1, EPSC));
                float cost = (beta_u[o] - 0.5f * __logf(sig1 + EPSC)) * S1;
                #pragma unroll
                for (int off = 8; off; off >>= 1) {
                    Co   += __shfl_xor_sync(0xffffffffu, Co,   off);
                    cc0  += __shfl_xor_sync(0xffffffffu, cc0,  off);
                    cost += __shfl_xor_sync(0xffffffffu, cost, off);
                }
                if (aa == 0) {
                    float arg = INVT1 * (beta_a[o] - cost);
                    float aj  = 1.0f / (1.0f + __expf(-arg));
                    st[ST_BASE + o] = __logf(aj + EPSC) - cc0 - Co;
                }
            }
            __threadfence_block();
            bar_arrive(BAR_FULL(b), 1024);     // stats[b] ready
        }
    } else {
        // ================= CONSUMER: fused E-step + M-step-2 =================
        const int wc = (t >> 5) - 16;        // 0..15
        const int l  = t & 31;
        const int h  = wc >> 3;              // o-half
        const int ib = wc & 7;
        const int m  = l & 15;
        const int ah = l >> 4;
        const int o  = h * 16 + m;
        float* Gp  = s_G  + wc * 272 + m * 17 + ah * 8;
        float* G2p = s_G2 + wc * 272 + m * 17 + ah * 8;

        for (int n = 0; n < POSPER; ++n) {
            const int pos = base + n;
            const int b   = n & 1;
            const float* st = smem + OFF_ST + b * ST_SIZE;
            const float* __restrict__ V = votes + (int64_t)pos * PERPOS;

            bar_sync(BAR_FULL(b), 1024);       // wait stats[b]

            uint64_t q2p[4], mqp[4];
            #pragma unroll
            for (int p = 0; p < 4; ++p) {
                const int aa0 = ah * 8 + 2 * p;
                q2p[p] = pk2(st[ST_Q2  + aa0 * 33 + o], st[ST_Q2  + (aa0+1) * 33 + o]);
                mqp[p] = pk2(st[ST_MQ1 + aa0 * 33 + o], st[ST_MQ1 + (aa0+1) * 33 + o]);
            }
            const float bse = st[ST_BASE + o];
            const float* sA8 = st + ST_A8;
            const int coff = o * 16 + ah * 8;

            #pragma unroll
            for (int r = 0; r < 4; ++r) {
                const int i = ib + 8 * r;
                uint64_t g0 = 0, g1 = 0, g2 = 0, g3 = 0;
                uint64_t e0 = 0, e1 = 0, e2 = 0, e3 = 0;
                float gr = 0.f, se = 0.f;

                #pragma unroll
                for (int j = 0; j < KHW; ++j) {
                    const float* pv = V + (size_t)(j * 32 + i) * 512 + coff;
                    U64x4 v = ldg_first32(pv);       // dead after this read
                    uint64_t t2 = 0;
                    t2 = fma2(v.a, fma2(v.a, q2p[0], mqp[0]), t2);
                    t2 = fma2(v.b, fma2(v.b, q2p[1], mqp[1]), t2);
                    t2 = fma2(v.c, fma2(v.c, q2p[2], mqp[2]), t2);
                    t2 = fma2(v.d, fma2(v.d, q2p[3], mqp[3]), t2);
                    float tlo, thi;
                    upk2(t2, tlo, thi);
                    float term = tlo + thi;
                    term += __shfl_xor_sync(0xffffffffu, term, 16); // join aa-halves
                    float e = __expf(bse - term);   // un-normalized, fp32-safe
                    se += e;
                    float ep = sA8[j * 32 + i] * e;
                    gr += ep;
                    uint64_t ep2 = pk2(ep, ep);
                    uint64_t rv;
                    rv = mul2(ep2, v.a); g0 = add2(g0, rv); e0 = fma2(rv, v.a, e0);
                    rv = mul2(ep2, v.b); g1 = add2(g1, rv); e1 = fma2(rv, v.b, e1);
                    rv = mul2(ep2, v.c); g2 = add2(g2, rv); e2 = fma2(rv, v.c, e2);
                    rv = mul2(ep2, v.d); g3 = add2(g3, rv); e3 = fma2(rv, v.d, e3);
                }

                // se over warp (each e counted twice by the two ah lanes)
                #pragma unroll
                for (int off = 16; off; off >>= 1)
                    se += __shfl_xor_sync(0xffffffffu, se, off);
                if (l == 0) s_se[r * 16 + wc] = se;
                bar_sync(8 + ib, 64);           // pair {wc, wc^8}
                const float invs =
                    1.0f / (0.5f * (s_se[r * 16 + wc] + s_se[r * 16 + (wc ^ 8)]));

                float lo, hi;
                if (r == 0) {
                    upk2(g0, lo, hi); Gp [0] = invs*lo; Gp [1] = invs*hi;
                    upk2(g1, lo, hi); Gp [2] = invs*lo; Gp [3] = invs*hi;
                    upk2(g2, lo, hi); Gp [4] = invs*lo; Gp [5] = invs*hi;
                    upk2(g3, lo, hi); Gp [6] = invs*lo; Gp [7] = invs*hi;
                    upk2(e0, lo, hi); G2p[0] = invs*lo; G2p[1] = invs*hi;
                    upk2(e1, lo, hi); G2p[2] = invs*lo; G2p[3] = invs*hi;
                    upk2(e2, lo, hi); G2p[4] = invs*lo; G2p[5] = invs*hi;
                    upk2(e3, lo, hi); G2p[6] = invs*lo; G2p[7] = invs*hi;
                    if (ah == 0) s_gr[wc * 16 + m] = invs * gr;
                } else {
                    upk2(g0, lo, hi); Gp [0] += invs*lo; Gp [1] += invs*hi;
                    upk2(g1, lo, hi); Gp [2] += invs*lo; Gp [3] += invs*hi;
                    upk2(g2, lo, hi); Gp [4] += invs*lo; Gp [5] += invs*hi;
                    upk2(g3, lo, hi); Gp [6] += invs*lo; Gp [7] += invs*hi;
                    upk2(e0, lo, hi); G2p[0] += invs*lo; G2p[1] += invs*hi;
                    upk2(e1, lo, hi); G2p[2] += invs*lo; G2p[3] += invs*hi;
                    upk2(e2, lo, hi); G2p[4] += invs*lo; G2p[5] += invs*hi;
                    upk2(e3, lo, hi); G2p[6] += invs*lo; G2p[7] += invs*hi;
                    if (ah == 0) s_gr[wc * 16 + m] += invs * gr;
                }
            }
            bar_sync(BAR_CONS, 512);           // G/G2/gr complete

            // final closure + output: consumer thread co = (o2, aa2)
            {
                const int co  = t - 512;
                const int o2  = co >> 4;
                const int aa2 = co & 15;
                const int h2  = o2 >> 4;
                const int m2  = o2 & 15;
                float crv  = 0.2f * st[ST_AVF  + o2 * 17 + aa2];
                float crv2 = 0.2f * st[ST_AV2F + o2 * 17 + aa2];
                float cr   = 0.2f * st[ST_S1];
                #pragma unroll
                for (int jb = 0; jb < 8; ++jb) {
                    const int w = h2 * 8 + jb;
                    crv  += s_G [w * 272 + m2 * 17 + aa2];
                    crv2 += s_G2[w * 272 + m2 * 17 + aa2];
                    cr   += s_gr[w * 16 + m2];
                }
                const float invR = 1.0f / (cr + EPSC);
                const float mu2  = crv * invR;
                out[pos * 512 + o2 * 16 + aa2] = mu2;             // poses

                const float sig2 =
                    fmaf(mu2 * mu2, cr, fmaf(-2.0f * mu2, crv, crv2)) * invR;
                float cost2 = (beta_u[o2] - 0.5f * __logf(sig2 + EPSC)) * cr;
                #pragma unroll
                for (int off = 8; off; off >>= 1)
                    cost2 += __shfl_xor_sync(0xffffffffu, cost2, off);
                if (aa2 == 0) {
                    float arg = INVT2 * (beta_a[o2] - cost2);
                    out[NPOS * 512 + pos * OO + o2] =
                        1.0f / (1.0f + __expf(-arg));             // acts
                }
            }
            bar_sync(BAR_CONS, 512);           // closure reads done before next n
            __threadfence_block();
            if (n < 2) bar_arrive(BAR_FREE(b), 1024);   // release stats[b]
        }
    }
}

extern "C" void kernel_launch(void* const* d_in, const int* in_sizes, int n_in,
                              void* d_out, int out_size) {
    const float* votes  = (const float*)d_in[0];
    const float* activ  = (const float*)d_in[1];
    const float* beta_a = (const float*)d_in[2];
    const float* beta_u = (const float*)d_in[3];

    cudaFuncSetAttribute(em_routing_kernel,
                         cudaFuncAttributeMaxDynamicSharedMemorySize,
                         SMEM_BYTES);

    em_routing_kernel<<<NCTA, NT, SMEM_BYTES>>>(
        votes, activ, beta_a, beta_u, (float*)d_out);
}

// round 16
// speedup vs baseline: 1.4109x; 1.0120x over previous
#include <cuda_runtime.h>
#include <math_constants.h>
#include <cstdint>

// EM routing, votes (16,6,6,3,3,32,32,4,4), 2 iterations.
// Warp-specialized persistent kernel: 144 CTAs x 1024 thr, 4 positions each.
// Producer warps (t<512) stream pass A of position n(+1) from HBM (evict_last).
// Consumer warps (t>=512) run fused E+M pass of position n from L2 (evict_first).
// L2 eviction hints require 256-bit loads on sm_103a -> v4.b64 everywhere.
#define NPOS   576
#define KHW    9
#define OO     32
#define KDIM   288
#define PERPOS (KDIM*512)
#define EPSC   1e-7f
#define INVT1  0.0005f        // 0.01*(1-0.95^1)
#define INVT2  0.00142625f    // 0.01*(1-0.95^3)

#define NT     1024
#define NCTA   144
#define POSPER 4

// stats buffer layout (floats)
#define ST_Q2   0      // 528  [aa*33+o]
#define ST_MQ1  528    // 528
#define ST_BASE 1056   // 32
#define ST_A8   1088   // 288
#define ST_AVF  1376   // 544  [o*17+aa]
#define ST_AV2F 1920   // 544
#define ST_S1   2464   // 8
#define ST_SIZE 2472

// smem layout (floats)
#define OFF_PA  0                       // 8192 producer slice partials (8 slices)
#define OFF_R1  8192                    // 288
#define OFF_ST  8480                    // 2*2472 = 4944
#define OFF_G   (OFF_ST + 2*ST_SIZE)    // 4352  consumer crv partials
#define OFF_G2  (OFF_G + 4352)          // 4352
#define OFF_GR  (OFF_G2 + 4352)         // 256
#define OFF_SE  (OFF_GR + 256)          // 64
#define SMEM_FLOATS (OFF_SE + 64)
#define SMEM_BYTES  (SMEM_FLOATS*4)     // ~90KB

extern __shared__ float smem[];

struct U64x4 { uint64_t a, b, c, d; };

__device__ __forceinline__ uint64_t pk2(float lo, float hi) {
    uint64_t r; asm("mov.b64 %0, {%1, %2};" : "=l"(r) : "f"(lo), "f"(hi)); return r;
}
__device__ __forceinline__ void upk2(uint64_t p, float& lo, float& hi) {
    asm("mov.b64 {%0, %1}, %2;" : "=f"(lo), "=f"(hi) : "l"(p));
}
__device__ __forceinline__ uint64_t mul2(uint64_t a, uint64_t b) {
    uint64_t r; asm("mul.rn.f32x2 %0, %1, %2;" : "=l"(r) : "l"(a), "l"(b)); return r;
}
__device__ __forceinline__ uint64_t add2(uint64_t a, uint64_t b) {
    uint64_t r; asm("add.rn.f32x2 %0, %1, %2;" : "=l"(r) : "l"(a), "l"(b)); return r;
}
__device__ __forceinline__ uint64_t fma2(uint64_t a, uint64_t b, uint64_t c) {
    uint64_t r; asm("fma.rn.f32x2 %0, %1, %2, %3;" : "=l"(r) : "l"(a), "l"(b), "l"(c)); return r;
}
// 256-bit streaming loads with L2 eviction-priority steering
__device__ __forceinline__ U64x4 ldg_last32(const void* p) {   // producer
    U64x4 v;
    asm volatile("ld.global.L2::evict_last.v4.b64 {%0, %1, %2, %3}, [%4];"
                 : "=l"(v.a), "=l"(v.b), "=l"(v.c), "=l"(v.d) : "l"(p));
    return v;
}
__device__ __forceinline__ U64x4 ldg_first32(const void* p) {  // consumer
    U64x4 v;
    asm volatile("ld.global.L2::evict_first.v4.b64 {%0, %1, %2, %3}, [%4];"
                 : "=l"(v.a), "=l"(v.b), "=l"(v.c), "=l"(v.d) : "l"(p));
    return v;
}
__device__ __forceinline__ void bar_sync(int id, int cnt) {
    asm volatile("bar.sync %0, %1;" :: "r"(id), "r"(cnt) : "memory");
}
__device__ __forceinline__ void bar_arrive(int id, int cnt) {
    asm volatile("bar.arrive %0, %1;" :: "r"(id), "r"(cnt) : "memory");
}

// barrier ids: FULL[b]=1+b, FREE[b]=3+b, producer=5, consumer=6, pair=8+ib
#define BAR_FULL(b) (1 + (b))
#define BAR_FREE(b) (3 + (b))
#define BAR_PROD    5
#define BAR_CONS    6

__global__ __launch_bounds__(NT, 1)
void em_routing_kernel(const float* __restrict__ votes,
                       const float* __restrict__ activ,
                       const float* __restrict__ beta_a,
                       const float* __restrict__ beta_u,
                       float* __restrict__ out)
{
    float* s_pA = smem + OFF_PA;
    float* s_R1 = smem + OFF_R1;
    float* s_G  = smem + OFF_G;
    float* s_G2 = smem + OFF_G2;
    float* s_gr = smem + OFF_GR;
    float* s_se = smem + OFF_SE;

    const int t    = threadIdx.x;                 // 0..1023
    const int base = blockIdx.x * POSPER;

    if (t < 512) {
        // ================= PRODUCER: pass A + stats closure =================
        for (int n = 0; n < POSPER; ++n) {
            const int   pos = base + n;
            const int   b   = n & 1;
            float* st = smem + OFF_ST + b * ST_SIZE;
            const float* __restrict__ V  = votes + (int64_t)pos * PERPOS;
            const float* __restrict__ Ai = activ + pos * KDIM;

            if (n >= 2) bar_sync(BAR_FREE(b), 1024);   // consumers freed buffer

            // prologue: R1 (private) + a8 (into stats buffer)
            if (t < KDIM) {
                float a = Ai[t];
                st[ST_A8 + t] = 0.8f * a;
                s_R1[t] = (0.8f * a + 0.2f) * (1.0f / 32.0f);
            }
            bar_sync(BAR_PROD, 512);
            if (t < 32) {
                float s = 0.f;
                #pragma unroll
                for (int k = t; k < KDIM; k += 32) s += s_R1[k];
                #pragma unroll
                for (int off = 16; off; off >>= 1)
                    s += __shfl_xor_sync(0xffffffffu, s, off);
                if (t == 0) st[ST_S1] = s;
            }

            // pass A: slice sl = t>>6 (8 slices x 36 k); 32B loads, evict_last
            {
                const int sl = t >> 6;               // 0..7
                const int c0 = (t & 63) * 8;         // 8 owned columns
                const float* gv = V + (size_t)(sl * 36) * 512 + c0;
                const float* r1 = s_R1 + sl * 36;
                uint64_t av0 = 0, av1 = 0, av2a = 0, av3 = 0;
                uint64_t q0 = 0, q1 = 0, q2 = 0, q3 = 0;
                #pragma unroll 6
                for (int k = 0; k < 36; ++k) {
                    U64x4 v = ldg_last32(gv + (size_t)k * 512);
                    float r = r1[k];
                    uint64_t r2 = pk2(r, r);
                    uint64_t rv;
                    rv = mul2(r2, v.a); av0  = add2(av0, rv); q0 = fma2(rv, v.a, q0);
                    rv = mul2(r2, v.b); av1  = add2(av1, rv); q1 = fma2(rv, v.b, q1);
                    rv = mul2(r2, v.c); av2a = add2(av2a, rv); q2 = fma2(rv, v.c, q2);
                    rv = mul2(r2, v.d); av3  = add2(av3, rv); q3 = fma2(rv, v.d, q3);
                }
                ulonglong2 w;
                w.x = av0; w.y = av1;
                *(ulonglong2*)(s_pA + sl * 1024 + c0) = w;
                w.x = av2a; w.y = av3;
                *(ulonglong2*)(s_pA + sl * 1024 + c0 + 4) = w;
                w.x = q0; w.y = q1;
                *(ulonglong2*)(s_pA + sl * 1024 + 512 + c0) = w;
                w.x = q2; w.y = q3;
                *(ulonglong2*)(s_pA + sl * 1024 + 512 + c0 + 4) = w;
            }
            bar_sync(BAR_PROD, 512);

            // stats closure: thread t = (o,aa)
            {
                float av = 0.f, av2 = 0.f;
                #pragma unroll
                for (int ss = 0; ss < 8; ++ss) {
                    av  += s_pA[ss * 1024 + t];
                    av2 += s_pA[ss * 1024 + 512 + t];
                }
                const int   o     = t >> 4;
                const int   aa    = t & 15;
                const float S1    = st[ST_S1];
                const float invS1 = 1.0f / (S1 + EPSC);
                const float mu1   = av * invS1;
                const float sig1  =
                    fmaf(mu1 * mu1, S1, fmaf(-2.0f * mu1, av, av2)) * invS1;
                const float i2s1  = 0.5f / sig1;      // no eps (matches ref)
                const float q1    = mu1 * i2s1;
                st[ST_Q2  + aa * 33 + o] = i2s1;
                st[ST_MQ1 + aa * 33 + o] = -2.0f * q1;
                st[ST_AVF  + o * 17 + aa] = av;
                st[ST_AV2F + o * 17 + aa] = av2;

                float Co   = mu1 * q1;
                float cc0  = __logf(fmaf(2.0f * CUDART_PI_F, sig1, EPSC));
                float cost = (beta_u[o] - 0.5f * __logf(sig1 + EPSC)) * S1;
                #pragma unroll
                for (int off = 8; off; off >>= 1) {
                    Co   += __shfl_xor_sync(0xffffffffu, Co,   off);
                    cc0  += __shfl_xor_sync(0xffffffffu, cc0,  off);
                    cost += __shfl_xor_sync(0xffffffffu, cost, off);
                }
                if (aa == 0) {
                    float arg = INVT1 * (beta_a[o] - cost);
                    float aj  = 1.0f / (1.0f + __expf(-arg));
                    st[ST_BASE + o] = __logf(aj + EPSC) - cc0 - Co;
                }
            }
            __threadfence_block();
            bar_arrive(BAR_FULL(b), 1024);     // stats[b] ready
        }
    } else {
        // ================= CONSUMER: fused E-step + M-step-2 =================
        const int wc = (t >> 5) - 16;        // 0..15
        const int l  = t & 31;
        const int h  = wc >> 3;              // o-half
        const int ib = wc & 7;
        const int m  = l & 15;
        const int ah = l >> 4;
        const int o  = h * 16 + m;
        float* Gp  = s_G  + wc * 272 + m * 17 + ah * 8;
        float* G2p = s_G2 + wc * 272 + m * 17 + ah * 8;

        for (int n = 0; n < POSPER; ++n) {
            const int pos = base + n;
            const int b   = n & 1;
            const float* st = smem + OFF_ST + b * ST_SIZE;
            const float* __restrict__ V = votes + (int64_t)pos * PERPOS;

            bar_sync(BAR_FULL(b), 1024);       // wait stats[b]

            uint64_t q2p[4], mqp[4];
            #pragma unroll
            for (int p = 0; p < 4; ++p) {
                const int aa0 = ah * 8 + 2 * p;
                q2p[p] = pk2(st[ST_Q2  + aa0 * 33 + o], st[ST_Q2  + (aa0+1) * 33 + o]);
                mqp[p] = pk2(st[ST_MQ1 + aa0 * 33 + o], st[ST_MQ1 + (aa0+1) * 33 + o]);
            }
            const float bse = st[ST_BASE + o];
            const float* sA8 = st + ST_A8;
            const int coff = o * 16 + ah * 8;

            #pragma unroll
            for (int r = 0; r < 4; ++r) {
                const int i = ib + 8 * r;
                uint64_t g0 = 0, g1 = 0, g2 = 0, g3 = 0;
                uint64_t e0 = 0, e1 = 0, e2 = 0, e3 = 0;
                float gr = 0.f, se = 0.f;

                #pragma unroll
                for (int j = 0; j < KHW; ++j) {
                    const float* pv = V + (size_t)(j * 32 + i) * 512 + coff;
                    U64x4 v = ldg_first32(pv);       // dead after this read
                    uint64_t t2 = 0;
                    t2 = fma2(v.a, fma2(v.a, q2p[0], mqp[0]), t2);
                    t2 = fma2(v.b, fma2(v.b, q2p[1], mqp[1]), t2);
                    t2 = fma2(v.c, fma2(v.c, q2p[2], mqp[2]), t2);
                    t2 = fma2(v.d, fma2(v.d, q2p[3], mqp[3]), t2);
                    float tlo, thi;
                    upk2(t2, tlo, thi);
                    float term = tlo + thi;
                    term += __shfl_xor_sync(0xffffffffu, term, 16); // join aa-halves
                    float e = __expf(bse - term);   // un-normalized, fp32-safe
                    se += e;
                    float ep = sA8[j * 32 + i] * e;
                    gr += ep;
                    uint64_t ep2 = pk2(ep, ep);
                    uint64_t rv;
                    rv = mul2(ep2, v.a); g0 = add2(g0, rv); e0 = fma2(rv, v.a, e0);
                    rv = mul2(ep2, v.b); g1 = add2(g1, rv); e1 = fma2(rv, v.b, e1);
                    rv = mul2(ep2, v.c); g2 = add2(g2, rv); e2 = fma2(rv, v.c, e2);
                    rv = mul2(ep2, v.d); g3 = add2(g3, rv); e3 = fma2(rv, v.d, e3);
                }

                // se over warp (each e counted twice by the two ah lanes)
                #pragma unroll
                for (int off = 16; off; off >>= 1)
                    se += __shfl_xor_sync(0xffffffffu, se, off);
                if (l == 0) s_se[r * 16 + wc] = se;
                bar_sync(8 + ib, 64);           // pair {wc, wc^8}
                const float invs =
                    1.0f / (0.5f * (s_se[r * 16 + wc] + s_se[r * 16 + (wc ^ 8)]));

                float lo, hi;
                if (r == 0) {
                    upk2(g0, lo, hi); Gp [0] = invs*lo; Gp [1] = invs*hi;
                    upk2(g1, lo, hi); Gp [2] = invs*lo; Gp [3] = invs*hi;
                    upk2(g2, lo, hi); Gp [4] = invs*lo; Gp [5] = invs*hi;
                    upk2(g3, lo, hi); Gp [6] = invs*lo; Gp [7] = invs*hi;
                    upk2(e0, lo, hi); G2p[0] = invs*lo; G2p[1] = invs*hi;
                    upk2(e1, lo, hi); G2p[2] = invs*lo; G2p[3] = invs*hi;
                    upk2(e2, lo, hi); G2p[4] = invs*lo; G2p[5] = invs*hi;
                    upk2(e3, lo, hi); G2p[6] = invs*lo; G2p[7] = invs*hi;
                    if (ah == 0) s_gr[wc * 16 + m] = invs * gr;
                } else {
                    upk2(g0, lo, hi); Gp [0] += invs*lo; Gp [1] += invs*hi;
                    upk2(g1, lo, hi); Gp [2] += invs*lo; Gp [3] += invs*hi;
                    upk2(g2, lo, hi); Gp [4] += invs*lo; Gp [5] += invs*hi;
                    upk2(g3, lo, hi); Gp [6] += invs*lo; Gp [7] += invs*hi;
                    upk2(e0, lo, hi); G2p[0] += invs*lo; G2p[1] += invs*hi;
                    upk2(e1, lo, hi); G2p[2] += invs*lo; G2p[3] += invs*hi;
                    upk2(e2, lo, hi); G2p[4] += invs*lo; G2p[5] += invs*hi;
                    upk2(e3, lo, hi); G2p[6] += invs*lo; G2p[7] += invs*hi;
                    if (ah == 0) s_gr[wc * 16 + m] += invs * gr;
                }
            }
            bar_sync(BAR_CONS, 512);           // G/G2/gr complete

            // final closure + output: consumer thread co = (o2, aa2)
            {
                const int co  = t - 512;
                const int o2  = co >> 4;
                const int aa2 = co & 15;
                const int h2  = o2 >> 4;
                const int m2  = o2 & 15;
                float crv  = 0.2f * st[ST_AVF  + o2 * 17 + aa2];
                float crv2 = 0.2f * st[ST_AV2F + o2 * 17 + aa2];
                float cr   = 0.2f * st[ST_S1];
                #pragma unroll
                for (int jb = 0; jb < 8; ++jb) {
                    const int w = h2 * 8 + jb;
                    crv  += s_G [w * 272 + m2 * 17 + aa2];
                    crv2 += s_G2[w * 272 + m2 * 17 + aa2];
                    cr   += s_gr[w * 16 + m2];
                }
                const float invR = 1.0f / (cr + EPSC);
                const float mu2  = crv * invR;
                out[pos * 512 + o2 * 16 + aa2] = mu2;             // poses

                const float sig2 =
                    fmaf(mu2 * mu2, cr, fmaf(-2.0f * mu2, crv, crv2)) * invR;
                float cost2 = (beta_u[o2] - 0.5f * __logf(sig2 + EPSC)) * cr;
                #pragma unroll
                for (int off = 8; off; off >>= 1)
                    cost2 += __shfl_xor_sync(0xffffffffu, cost2, off);
                if (aa2 == 0) {
                    float arg = INVT2 * (beta_a[o2] - cost2);
                    out[NPOS * 512 + pos * OO + o2] =
                        1.0f / (1.0f + __expf(-arg));             // acts
                }
            }
            bar_sync(BAR_CONS, 512);           // closure reads done before next n
            __threadfence_block();
            if (n < 2) bar_arrive(BAR_FREE(b), 1024);   // release stats[b]
        }
    }
}

extern "C" void kernel_launch(void* const* d_in, const int* in_sizes, int n_in,
                              void* d_out, int out_size) {
    const float* votes  = (const float*)d_in[0];
    const float* activ  = (const float*)d_in[1];
    const float* beta_a = (const float*)d_in[2];
    const float* beta_u = (const float*)d_in[3];

    cudaFuncSetAttribute(em_routing_kernel,
                         cudaFuncAttributeMaxDynamicSharedMemorySize,
                         SMEM_BYTES);

    em_routing_kernel<<<NCTA, NT, SMEM_BYTES>>>(
        votes, activ, beta_a, beta_u, (float*)d_out);
}